// round 2
// baseline (speedup 1.0000x reference)
#include <cuda_runtime.h>
#include <cstddef>

#define B_  16
#define C_  1024
#define T_  16
#define HW_ 360      // H*W = 12*30
#define K_  120
#define ROWS_ 482    // 1 + 120 + 1 + 360
#define CHUNKS 16
#define CC 64        // channels per chunk (CHUNKS*CC == C_)
#define STRIDE_T (T_*HW_)   // 5760: stride between consecutive c for fixed (b,t,p)

// Scratch (no allocations allowed in kernel_launch)
__device__ double g_partial[B_][CHUNKS][HW_];
__device__ int    g_topk[B_][K_];

// ---------------------------------------------------------------------------
// K1: partial dot products  d[b,p] += sum_{c in chunk} cls[b,0,c] * x[b,c,0,p]
// grid (CHUNKS, B), 384 threads (360 active lanes over p). Reads are fully
// coalesced: for fixed c, x[b,c,0,0:360] is 1440 contiguous bytes.
// ---------------------------------------------------------------------------
__global__ void scores_kernel(const float* __restrict__ x,
                              const float* __restrict__ cls) {
    const int chunk = blockIdx.x;
    const int b     = blockIdx.y;
    const int tid   = threadIdx.x;

    __shared__ float cls_s[CC];
    if (tid < CC)
        cls_s[tid] = cls[(size_t)b * T_ * C_ + (size_t)chunk * CC + tid];  // t = 0
    __syncthreads();

    if (tid >= HW_) return;

    const float* xr = x + ((size_t)(b * C_ + chunk * CC)) * STRIDE_T + tid; // t=0, p=tid
    double acc = 0.0;
#pragma unroll 8
    for (int j = 0; j < CC; ++j)
        acc += (double)cls_s[j] * (double)xr[(size_t)j * STRIDE_T];

    g_partial[b][chunk][tid] = acc;
}

// ---------------------------------------------------------------------------
// K2: per-batch chunk reduction (deterministic order), bitonic top-K of 512
// (value descending, index ascending — matches jax.lax.top_k semantics),
// plus the two cls rows of the output.  grid (B), 256 threads.
// ---------------------------------------------------------------------------
__global__ void topk_kernel(const float* __restrict__ cls,
                            float* __restrict__ out) {
    const int b   = blockIdx.x;
    const int tid = threadIdx.x;

    __shared__ double sval[512];
    __shared__ int    sidx[512];

    for (int i = tid; i < 512; i += 256) {
        double s;
        if (i < HW_) {
            s = 0.0;
#pragma unroll
            for (int j = 0; j < CHUNKS; ++j) s += g_partial[b][j][i];
        } else {
            s = -1e300;   // pad below any real score
        }
        sval[i] = s;
        sidx[i] = i;
    }
    __syncthreads();

    // Bitonic sort, 512 elements, key order = (value desc, index asc)
    for (int k = 2; k <= 512; k <<= 1) {
        for (int j = k >> 1; j > 0; j >>= 1) {
            for (int i = tid; i < 512; i += 256) {
                const int ixj = i ^ j;
                if (ixj > i) {
                    const double v1 = sval[i], v2 = sval[ixj];
                    const int    i1 = sidx[i], i2 = sidx[ixj];
                    const bool iFirst = (v1 > v2) || (v1 == v2 && i1 < i2);
                    const bool up = ((i & k) == 0);
                    if (up != iFirst) {
                        sval[i] = v2; sval[ixj] = v1;
                        sidx[i] = i2; sidx[ixj] = i1;
                    }
                }
            }
            __syncthreads();
        }
    }

    if (tid < K_) g_topk[b][tid] = sidx[tid];

    // cls rows: out row 0 = cls[b,0,:], out row 121 = cls[b,1,:]
    for (int c = tid; c < C_; c += 256) {
        out[((size_t)b * ROWS_ + 0)   * C_ + c] = cls[(size_t)b * T_ * C_ + c];
        out[((size_t)b * ROWS_ + 121) * C_ + c] = cls[(size_t)b * T_ * C_ + C_ + c];
    }
}

// ---------------------------------------------------------------------------
// K3: assemble transposed token rows via 32x32 smem tiles.
//   blockIdx.y <  4  : gather rows 1..120   out[b,1+k,c]   = x[b,c,0,topk[b][k]]
//   blockIdx.y >= 4  : global rows 122..481 out[b,122+p,c] = x[b,c,1,p]
// grid (32 c-tiles, 16, B), block (32,8). Loads coalesced over p; stores
// coalesced over c; 33-pitch smem avoids bank conflicts on the transpose read.
// ---------------------------------------------------------------------------
__global__ void assemble_kernel(const float* __restrict__ x,
                                float* __restrict__ out) {
    const int ct = blockIdx.x;           // c tile
    const int by = blockIdx.y;
    const int b  = blockIdx.z;
    const int tx = threadIdx.x;          // 0..31
    const int ty = threadIdx.y;          // 0..7
    const int c0 = ct * 32;

    __shared__ float tile[32][33];
    __shared__ int   pidx[32];

    if (by < 4) {
        // ---- gather of top-K t=0 tokens ----
        const int k0 = by * 32;
        if (ty == 0) {
            const int k = k0 + tx;
            pidx[tx] = (k < K_) ? g_topk[b][k] : -1;
        }
        __syncthreads();

        const int p = pidx[tx];
        if (p >= 0) {
#pragma unroll
            for (int i = 0; i < 4; ++i) {
                const int ci = ty + 8 * i;
                tile[ci][tx] = x[((size_t)(b * C_ + c0 + ci)) * STRIDE_T + p]; // t=0
            }
        }
        __syncthreads();

#pragma unroll
        for (int i = 0; i < 4; ++i) {
            const int kr = k0 + ty + 8 * i;
            if (kr < K_)
                out[((size_t)b * ROWS_ + 1 + kr) * C_ + c0 + tx] = tile[tx][ty + 8 * i];
        }
    } else {
        // ---- full t=1 slice transpose ----
        const int p0 = (by - 4) * 32;
        const int p  = p0 + tx;
        if (p < HW_) {
#pragma unroll
            for (int i = 0; i < 4; ++i) {
                const int ci = ty + 8 * i;
                tile[ci][tx] = x[((size_t)(b * C_ + c0 + ci)) * STRIDE_T + HW_ + p]; // t=1
            }
        }
        __syncthreads();

#pragma unroll
        for (int i = 0; i < 4; ++i) {
            const int pr = p0 + ty + 8 * i;
            if (pr < HW_)
                out[((size_t)b * ROWS_ + 122 + pr) * C_ + c0 + tx] = tile[tx][ty + 8 * i];
        }
    }
}

// ---------------------------------------------------------------------------
extern "C" void kernel_launch(void* const* d_in, const int* in_sizes, int n_in,
                              void* d_out, int out_size) {
    const float* x   = (const float*)d_in[0];
    const float* cls = (const float*)d_in[1];
    // Defensive: x is the huge tensor (B*C*T*H*W = 94,371,840), cls is 262,144.
    if (n_in >= 2 && in_sizes[0] < in_sizes[1]) {
        const float* tmp = x; x = cls; cls = tmp;
    }
    float* out = (float*)d_out;

    scores_kernel  <<<dim3(CHUNKS, B_), 384>>>(x, cls);
    topk_kernel    <<<B_, 256>>>(cls, out);
    assemble_kernel<<<dim3(32, 16, B_), dim3(32, 8)>>>(x, out);
}

// round 3
// speedup vs baseline: 1.6609x; 1.6609x over previous
#include <cuda_runtime.h>
#include <cstddef>

#define B_  16
#define C_  1024
#define T_  16
#define HW_ 360      // H*W = 12*30
#define K_  120
#define ROWS_ 482    // 1 + 120 + 1 + 360
#define CHUNKS 16
#define CC 64        // channels per chunk (CHUNKS*CC == C_)
#define STRIDE_T (T_*HW_)   // 5760 floats between consecutive c for fixed (b,t,p)

// Scratch (no allocations allowed in kernel_launch)
__device__ float g_partial[B_][CHUNKS][HW_];
__device__ int   g_topk[B_][K_];

// ---------------------------------------------------------------------------
// K1: partial dot products  d[b,p] += sum_{c in chunk} cls[b,0,c] * x[b,c,0,p]
// grid (CHUNKS, B), 192 threads; each active thread owns two p's via float2.
// fp32 FFMA with two paired accumulators (chain length CC/2 = 32).
// ---------------------------------------------------------------------------
__global__ void scores_kernel(const float* __restrict__ x,
                              const float* __restrict__ cls) {
    const int chunk = blockIdx.x;
    const int b     = blockIdx.y;
    const int tid   = threadIdx.x;

    __shared__ float cls_s[CC];
    if (tid < CC)
        cls_s[tid] = cls[(size_t)b * T_ * C_ + (size_t)chunk * CC + tid];  // t = 0
    __syncthreads();

    if (tid >= HW_ / 2) return;   // 180 active lanes, p = 2*tid, 2*tid+1

    const float2* xr = (const float2*)(x + ((size_t)(b * C_ + chunk * CC)) * STRIDE_T) + tid;
    const size_t cstride2 = STRIDE_T / 2;   // 2880 float2 between c rows

    float2 a0 = make_float2(0.f, 0.f);
    float2 a1 = make_float2(0.f, 0.f);
#pragma unroll 8
    for (int j = 0; j < CC; j += 2) {
        const float2 v0 = xr[(size_t)j       * cstride2];
        const float2 v1 = xr[(size_t)(j + 1) * cstride2];
        const float  w0 = cls_s[j];
        const float  w1 = cls_s[j + 1];
        a0.x = fmaf(w0, v0.x, a0.x);
        a0.y = fmaf(w0, v0.y, a0.y);
        a1.x = fmaf(w1, v1.x, a1.x);
        a1.y = fmaf(w1, v1.y, a1.y);
    }

    g_partial[b][chunk][2 * tid]     = a0.x + a1.x;
    g_partial[b][chunk][2 * tid + 1] = a0.y + a1.y;
}

// ---------------------------------------------------------------------------
// K2: per-batch chunk reduction (deterministic order, double), bitonic top-K
// of 512 (value descending, index ascending — matches jax.lax.top_k), plus
// the two cls rows of the output.  grid (B), 256 threads.
// ---------------------------------------------------------------------------
__global__ void topk_kernel(const float* __restrict__ cls,
                            float* __restrict__ out) {
    const int b   = blockIdx.x;
    const int tid = threadIdx.x;

    __shared__ double sval[512];
    __shared__ int    sidx[512];

    for (int i = tid; i < 512; i += 256) {
        double s;
        if (i < HW_) {
            s = 0.0;
#pragma unroll
            for (int j = 0; j < CHUNKS; ++j) s += (double)g_partial[b][j][i];
        } else {
            s = -1e300;   // pad below any real score
        }
        sval[i] = s;
        sidx[i] = i;
    }
    __syncthreads();

    // Bitonic sort, 512 elements, key order = (value desc, index asc)
    for (int k = 2; k <= 512; k <<= 1) {
        for (int j = k >> 1; j > 0; j >>= 1) {
            for (int i = tid; i < 512; i += 256) {
                const int ixj = i ^ j;
                if (ixj > i) {
                    const double v1 = sval[i], v2 = sval[ixj];
                    const int    i1 = sidx[i], i2 = sidx[ixj];
                    const bool iFirst = (v1 > v2) || (v1 == v2 && i1 < i2);
                    const bool up = ((i & k) == 0);
                    if (up != iFirst) {
                        sval[i] = v2; sval[ixj] = v1;
                        sidx[i] = i2; sidx[ixj] = i1;
                    }
                }
            }
            __syncthreads();
        }
    }

    if (tid < K_) g_topk[b][tid] = sidx[tid];

    // cls rows: out row 0 = cls[b,0,:], out row 121 = cls[b,1,:]
    for (int c = tid; c < C_; c += 256) {
        out[((size_t)b * ROWS_ + 0)   * C_ + c] = cls[(size_t)b * T_ * C_ + c];
        out[((size_t)b * ROWS_ + 121) * C_ + c] = cls[(size_t)b * T_ * C_ + C_ + c];
    }
}

// ---------------------------------------------------------------------------
// K3: assemble transposed token rows via 32x32 smem tiles.
//   blockIdx.y <  4  : gather rows 1..120   out[b,1+k,c]   = x[b,c,0,topk[b][k]]
//   blockIdx.y >= 4  : global rows 122..481 out[b,122+p,c] = x[b,c,1,p]
// grid (32 c-tiles, 16, B), block (32,8). Gather reads hit L2 (t=0 slice was
// just streamed by K1); stores coalesced over c; 33-pitch smem kills bank
// conflicts on the transpose read.
// ---------------------------------------------------------------------------
__global__ void assemble_kernel(const float* __restrict__ x,
                                float* __restrict__ out) {
    const int ct = blockIdx.x;           // c tile
    const int by = blockIdx.y;
    const int b  = blockIdx.z;
    const int tx = threadIdx.x;          // 0..31
    const int ty = threadIdx.y;          // 0..7
    const int c0 = ct * 32;

    __shared__ float tile[32][33];
    __shared__ int   pidx[32];

    if (by < 4) {
        // ---- gather of top-K t=0 tokens ----
        const int k0 = by * 32;
        if (ty == 0) {
            const int k = k0 + tx;
            pidx[tx] = (k < K_) ? g_topk[b][k] : -1;
        }
        __syncthreads();

        const int p = pidx[tx];
        if (p >= 0) {
#pragma unroll
            for (int i = 0; i < 4; ++i) {
                const int ci = ty + 8 * i;
                tile[ci][tx] = x[((size_t)(b * C_ + c0 + ci)) * STRIDE_T + p]; // t=0
            }
        }
        __syncthreads();

#pragma unroll
        for (int i = 0; i < 4; ++i) {
            const int kr = k0 + ty + 8 * i;
            if (kr < K_)
                out[((size_t)b * ROWS_ + 1 + kr) * C_ + c0 + tx] = tile[tx][ty + 8 * i];
        }
    } else {
        // ---- full t=1 slice transpose ----
        const int p0 = (by - 4) * 32;
        const int p  = p0 + tx;
        if (p < HW_) {
#pragma unroll
            for (int i = 0; i < 4; ++i) {
                const int ci = ty + 8 * i;
                tile[ci][tx] = x[((size_t)(b * C_ + c0 + ci)) * STRIDE_T + HW_ + p]; // t=1
            }
        }
        __syncthreads();

#pragma unroll
        for (int i = 0; i < 4; ++i) {
            const int pr = p0 + ty + 8 * i;
            if (pr < HW_)
                out[((size_t)b * ROWS_ + 122 + pr) * C_ + c0 + tx] = tile[tx][ty + 8 * i];
        }
    }
}

// ---------------------------------------------------------------------------
extern "C" void kernel_launch(void* const* d_in, const int* in_sizes, int n_in,
                              void* d_out, int out_size) {
    const float* x   = (const float*)d_in[0];
    const float* cls = (const float*)d_in[1];
    // Defensive: x is the huge tensor (94,371,840 elems), cls is 262,144.
    if (n_in >= 2 && in_sizes[0] < in_sizes[1]) {
        const float* tmp = x; x = cls; cls = tmp;
    }
    float* out = (float*)d_out;

    scores_kernel  <<<dim3(CHUNKS, B_), 192>>>(x, cls);
    topk_kernel    <<<B_, 256>>>(cls, out);
    assemble_kernel<<<dim3(32, 16, B_), dim3(32, 8)>>>(x, out);
}